// round 16
// baseline (speedup 1.0000x reference)
#include <cuda_runtime.h>

#define BATCH   8
#define NNODE   256
#define XHIN    9
#define XHHID   64
#define POSHID  192
#define TWO_PI_F 6.283185307179586f
#define NTILE   8      // 256 / 32
#define NPAIR   36     // NTILE*(NTILE+1)/2
#define GRIDSZ  (BATCH * NPAIR)            // 288
#define DYN_FLOATS 14848                   // max(9216 phase1, 14848 phase2)
#define DYN_BYTES  (DYN_FLOATS * 4)        // 59392

// Partial PE sums: [batch][slot][row][freq], freq = [sin 0..63, cos 64..127].
// Row-tile T gets j-side partials in slots 0..T-1, i-side in slots T..7 ->
// all 8 slots covered exactly once => no atomics, no zero-init.
__device__ float g_Spart[BATCH][NTILE][NNODE][128];
__device__ unsigned g_ctr;                 // monotonic grid-barrier counter

// ---------------------------------------------------------------------------
// Fused persistent kernel, grid = 288, block = 256, dyn smem = 59392B.
// Phase 1 (all 288 blocks): pair-tile sin/cos accumulation (off-diag pairs
//   computed once, both sides); diagonal blocks also do batch mean + 9->64
//   xh embedding. Writes g_Spart.
// Grid barrier (all blocks co-resident by __launch_bounds__(256,2):
//   2/SM * 148 = 296 >= 288; monotonic counter => replay-safe).
// Phase 2 (blocks 0..255): projection GEMM, 16 rows x 96 cols per block,
//   W_pos half staged into the reused dynamic smem; g_Spart is L2-hot.
// ---------------------------------------------------------------------------
__global__ __launch_bounds__(256, 2) void fused_ditemb(
    const float* __restrict__ xh,
    const float* __restrict__ node_mask,
    const float* __restrict__ W_xh,
    const float* __restrict__ b_xh,
    const float* __restrict__ W_pos,
    const float* __restrict__ b_pos,
    float* __restrict__ out)
{
    extern __shared__ float dyn[];
    // phase-1 views
    float2* SjP  = (float2*)dyn;                 // [8][16][32] float2 (32KB)
    float*  a_sm = dyn + 8192;                   // [1024]
    // phase-2 views (reuse)
    float*  sWp  = dyn;                          // [128*96] (48KB)
    float4* S4   = (float4*)(dyn + 12288);       // [128][5] padded quads (flat)

    __shared__ float xi[3][32], xj[3][32];
    __shared__ float mi_sm[32], mj_sm[32];
    __shared__ float wred[8][4];
    __shared__ float sW[XHIN * XHHID];
    __shared__ float sB[XHHID];
    __shared__ float hs[32][6];

    int t = threadIdx.x;
    int w = t >> 5, l = t & 31;

    // ======================= PHASE 1: pair tiles ===========================
    {
        int b = blockIdx.x / NPAIR;
        int p = blockIdx.x % NPAIR;
        int ti = 0, rem = p;
        while (rem >= NTILE - ti) { rem -= NTILE - ti; ti++; }
        int tj = ti + rem;
        bool offdiag = (ti != tj);

        int r = w & 3;
        int g = w >> 2;

        if (t < 32) {
            int rowg = b * NNODE + ti * 32 + t;
            xi[0][t] = xh[rowg * XHIN + 0];
            xi[1][t] = xh[rowg * XHIN + 1];
            xi[2][t] = xh[rowg * XHIN + 2];
            mi_sm[t] = node_mask[rowg];
        } else if (t < 64) {
            int tt = t - 32;
            int rowg = b * NNODE + tj * 32 + tt;
            xj[0][tt] = xh[rowg * XHIN + 0];
            xj[1][tt] = xh[rowg * XHIN + 1];
            xj[2][tt] = xh[rowg * XHIN + 2];
            mj_sm[tt] = node_mask[rowg];
        }

        if (!offdiag) {
            // full-batch masked reduction for mean/N (butterfly)
            int rowg = b * NNODE + t;
            float m  = node_mask[rowg];
            float y0 = xh[rowg * XHIN + 0] * m;
            float y1 = xh[rowg * XHIN + 1] * m;
            float y2 = xh[rowg * XHIN + 2] * m;
            float y3 = m;
            #pragma unroll
            for (int off = 16; off > 0; off >>= 1) {
                y0 += __shfl_xor_sync(0xffffffffu, y0, off);
                y1 += __shfl_xor_sync(0xffffffffu, y1, off);
                y2 += __shfl_xor_sync(0xffffffffu, y2, off);
                y3 += __shfl_xor_sync(0xffffffffu, y3, off);
            }
            if (l == 0) { wred[w][0] = y0; wred[w][1] = y1; wred[w][2] = y2; wred[w][3] = y3; }

            for (int i = t; i < XHIN * XHHID; i += 256) sW[i] = W_xh[i];
            if (t < XHHID) sB[t] = b_xh[t];
            if (t < 192) {
                int rr = t / 6, cc = t % 6;
                hs[rr][cc] = xh[(size_t)(b * NNODE + ti * 32 + rr) * XHIN + 3 + cc];
            }
        }
        __syncthreads();

        if (!offdiag) {
            float sx = 0.f, sy = 0.f, sz = 0.f, sn = 0.f;
            #pragma unroll
            for (int ww = 0; ww < 8; ww++) {
                sx += wred[ww][0]; sy += wred[ww][1];
                sz += wred[ww][2]; sn += wred[ww][3];
            }
            float mean0 = sx / sn, mean1 = sy / sn, mean2 = sz / sn;

            // xh embedding: 2048 outputs, 8 per thread, coalesced over o
            #pragma unroll
            for (int e = 0; e < 8; e++) {
                int v = e * 256 + t;
                int rr = v >> 6, o = v & 63;
                float mr  = mi_sm[rr];
                float xc0 = (xi[0][rr] - mean0) * mr;
                float xc1 = (xi[1][rr] - mean1) * mr;
                float xc2 = (xi[2][rr] - mean2) * mr;
                float acc = sB[o];
                acc = fmaf(xc0,       sW[0 * XHHID + o], acc);
                acc = fmaf(xc1,       sW[1 * XHHID + o], acc);
                acc = fmaf(xc2,       sW[2 * XHHID + o], acc);
                acc = fmaf(hs[rr][0], sW[3 * XHHID + o], acc);
                acc = fmaf(hs[rr][1], sW[4 * XHHID + o], acc);
                acc = fmaf(hs[rr][2], sW[5 * XHHID + o], acc);
                acc = fmaf(hs[rr][3], sW[6 * XHHID + o], acc);
                acc = fmaf(hs[rr][4], sW[7 * XHHID + o], acc);
                acc = fmaf(hs[rr][5], sW[8 * XHHID + o], acc);
                out[(size_t)(b * NNODE + ti * 32 + rr) * 256 + o] = acc * mr;
            }
        }

        // angles for the 32x32 tile (mean cancels in differences)
        #pragma unroll
        for (int k = 0; k < 4; k++) {
            int q = t + k * 256;
            int i = q & 31, j = q >> 5;
            float dx = xi[0][i] - xj[0][j];
            float dy = xi[1][i] - xj[1][j];
            float dz = xi[2][i] - xj[2][j];
            float sq = fmaxf(fmaf(dx, dx, fmaf(dy, dy, dz * dz)), 0.0f);
            a_sm[j * 32 + i] = TWO_PI_F * sqrtf(sq + 1e-12f);
        }
        __syncthreads();

        const float c1 = 0.10381025296522944f;       // log2(100)/64
        float f = exp2f((float)(g * 32 + l) * c1);

        float mi[8];
        #pragma unroll
        for (int k = 0; k < 8; k++) mi[k] = mi_sm[r * 8 + k];

        float ssA[8], ccA[8];
        #pragma unroll
        for (int k = 0; k < 8; k++) { ssA[k] = 0.f; ccA[k] = 0.f; }

        for (int h = 0; h < 2; h++) {
            #pragma unroll 4
            for (int j2 = 0; j2 < 16; j2++) {
                int j = h * 16 + j2;
                float mj = mj_sm[j];
                const float4* ap = (const float4*)&a_sm[j * 32 + r * 8];
                float4 a0 = ap[0];
                float4 a1 = ap[1];
                float av[8] = {a0.x, a0.y, a0.z, a0.w, a1.x, a1.y, a1.z, a1.w};
                float sjs = 0.f, sjc = 0.f;
                #pragma unroll
                for (int k = 0; k < 8; k++) {
                    float ang = av[k] * f;
                    float s = __sinf(ang);
                    float c = __cosf(ang);
                    ssA[k] = fmaf(mj, s, ssA[k]);
                    ccA[k] = fmaf(mj, c, ccA[k]);
                    sjs    = fmaf(mi[k], s, sjs);
                    sjc    = fmaf(mi[k], c, sjc);
                }
                if (offdiag) SjP[(w * 16 + j2) * 32 + l] = make_float2(sjs, sjc);
            }

            if (offdiag) {
                __syncthreads();
                #pragma unroll
                for (int k = 0; k < 4; k++) {
                    int idx = t + k * 256;
                    int gg  = idx >> 9;
                    int jj  = (idx >> 5) & 15;
                    int ll  = idx & 31;
                    float2 v0 = SjP[((gg * 4 + 0) * 16 + jj) * 32 + ll];
                    float2 v1 = SjP[((gg * 4 + 1) * 16 + jj) * 32 + ll];
                    float2 v2 = SjP[((gg * 4 + 2) * 16 + jj) * 32 + ll];
                    float2 v3 = SjP[((gg * 4 + 3) * 16 + jj) * 32 + ll];
                    float ss = (v0.x + v1.x) + (v2.x + v3.x);
                    float cc = (v0.y + v1.y) + (v2.y + v3.y);
                    float* rp = &g_Spart[b][ti][tj * 32 + h * 16 + jj][0];
                    rp[gg * 32 + ll]      = ss;
                    rp[64 + gg * 32 + ll] = cc;
                }
                __syncthreads();
            }
        }

        float* basei = &g_Spart[b][tj][ti * 32][0];
        #pragma unroll
        for (int k = 0; k < 8; k++) {
            float* rp = basei + (r * 8 + k) * 128;
            rp[g * 32 + l]      = ssA[k];
            rp[64 + g * 32 + l] = ccA[k];
        }
    }

    // ======================= GRID BARRIER ==================================
    __syncthreads();
    if (t == 0) {
        __threadfence();
        unsigned old = atomicAdd(&g_ctr, 1u);
        unsigned target = (old / GRIDSZ + 1u) * GRIDSZ;
        volatile unsigned* vc = &g_ctr;
        while (*vc < target) { }
        __threadfence();
    }
    __syncthreads();

    // ======================= PHASE 2: projection GEMM ======================
    if (blockIdx.x < 256) {
        int cb = blockIdx.x & 1;              // col half: cols cb*96 ..
        int rg = blockIdx.x >> 1;             // 0..127
        int b2 = rg >> 4;
        int i0 = (rg & 15) << 4;              // 16 rows

        // stage W_pos half: 128 rows x 24 float4 (48KB)
        {
            const float4* src = (const float4*)W_pos;   // 48 float4 per k-row
            float4*       dst = (float4*)sWp;           // 24 float4 per k-row
            #pragma unroll
            for (int ii = 0; ii < 12; ii++) {
                int idx = t + (ii << 8);                // 0..3071
                int kk = idx / 24, c4 = idx % 24;
                dst[kk * 24 + c4] = src[kk * 48 + cb * 24 + c4];
            }
        }

        // slot sums -> raw S [k][20] padded (L2-hot reads)
        {
            float* Ssc = (float*)S4;
            #pragma unroll
            for (int ii = 0; ii < 8; ii++) {
                int v = t + (ii << 8);                  // 0..2047
                int rv = v >> 7, fv = v & 127;
                float s = 0.f;
                #pragma unroll
                for (int slot = 0; slot < NTILE; slot++)
                    s += g_Spart[b2][slot][i0 + rv][fv];
                Ssc[fv * 20 + rv] = s;
            }
        }

        // N reduction (butterfly; one barrier total in phase 2)
        {
            float m = node_mask[b2 * NNODE + t];
            #pragma unroll
            for (int off = 16; off > 0; off >>= 1)
                m += __shfl_xor_sync(0xffffffffu, m, off);
            if (l == 0) wred[w][0] = m;
        }
        __syncthreads();

        float Ns = 0.f;
        #pragma unroll
        for (int ww = 0; ww < 8; ww++) Ns += wred[ww][0];
        float sc0 = 1.0f / Ns;
        float sc1 = 256.0f / Ns;

        // matvec: thread = (col c of 96, row-octet rh)
        if (t < 192) {
            int rh = t / 96;
            int c  = t - rh * 96;
            float acc[8];
            #pragma unroll
            for (int e = 0; e < 8; e++) acc[e] = 0.f;
            #pragma unroll 4
            for (int k = 0; k < 128; k++) {
                float4 s0 = S4[k * 5 + rh * 2];         // broadcast LDS.128
                float4 s1 = S4[k * 5 + rh * 2 + 1];
                float  wv = sWp[k * 96 + c];            // conflict-free LDS.32
                acc[0] = fmaf(s0.x, wv, acc[0]);
                acc[1] = fmaf(s0.y, wv, acc[1]);
                acc[2] = fmaf(s0.z, wv, acc[2]);
                acc[3] = fmaf(s0.w, wv, acc[3]);
                acc[4] = fmaf(s1.x, wv, acc[4]);
                acc[5] = fmaf(s1.y, wv, acc[5]);
                acc[6] = fmaf(s1.z, wv, acc[6]);
                acc[7] = fmaf(s1.w, wv, acc[7]);
            }
            int col = cb * 96 + c;
            float bp = b_pos[col] * sc1;
            int rbase = b2 * NNODE + i0 + rh * 8;
            #pragma unroll
            for (int e = 0; e < 8; e++) {
                float mke = node_mask[rbase + e];
                out[(size_t)(rbase + e) * 256 + 64 + col]
                    = (acc[e] * sc0 * mke + bp) * mke;
            }
        }
    }
}

extern "C" void kernel_launch(void* const* d_in, const int* in_sizes, int n_in,
                              void* d_out, int out_size)
{
    // inputs (metadata order): t, xh, node_mask, edge_mask, W_xh, b_xh, W_pos, b_pos
    const float* xh        = (const float*)d_in[1];
    const float* node_mask = (const float*)d_in[2];
    const float* W_xh      = (const float*)d_in[4];
    const float* b_xh      = (const float*)d_in[5];
    const float* W_pos     = (const float*)d_in[6];
    const float* b_pos     = (const float*)d_in[7];
    float* out = (float*)d_out;

    cudaFuncSetAttribute(fused_ditemb,
                         cudaFuncAttributeMaxDynamicSharedMemorySize,
                         DYN_BYTES);

    fused_ditemb<<<GRIDSZ, 256, DYN_BYTES>>>(xh, node_mask, W_xh, b_xh,
                                             W_pos, b_pos, out);
}

// round 17
// speedup vs baseline: 1.0089x; 1.0089x over previous
#include <cuda_runtime.h>

#define BATCH   8
#define NNODE   256
#define XHIN    9
#define XHHID   64
#define POSHID  192
#define TWO_PI_F 6.283185307179586f
#define NTILE   8      // 256 / 32
#define NPAIR   36     // NTILE*(NTILE+1)/2
#define GRIDSZ  (BATCH * NPAIR)            // 288
#define DYN_FLOATS 14848                   // max(9216 phase1, 14848 phase2)
#define DYN_BYTES  (DYN_FLOATS * 4)        // 59392

// Partial PE sums: [batch][slot][row][freq], freq = [sin 0..63, cos 64..127].
// Row-tile T gets j-side partials in slots 0..T-1, i-side in slots T..7 ->
// all 8 slots covered exactly once => no atomics, no zero-init.
__device__ float g_Spart[BATCH][NTILE][NNODE][128];
__device__ unsigned g_ctr;                 // monotonic grid-barrier counter

// ---------------------------------------------------------------------------
// Fused persistent kernel, grid = 288, block = 256, dyn smem = 59392B.
// __launch_bounds__(256,3): regs<=85, 3 blocks/SM (768 thr, ~195KB smem)
// -> 288 blocks all co-resident (<= 444) AND 6 warps/SMSP for MUFU feeding.
// Phase 1 (all blocks): pair-tile sin/cos accumulation; diagonal blocks also
//   do batch mean + 9->64 xh embedding. Writes g_Spart.
// Grid barrier: monotonic counter (replay-safe), nanosleep spin.
// Phase 2 (blocks 0..255): projection GEMM, 16 rows x 96 cols per block,
//   W_pos half staged into the reused dynamic smem; g_Spart is L2-hot.
// ---------------------------------------------------------------------------
__global__ __launch_bounds__(256, 3) void fused_ditemb(
    const float* __restrict__ xh,
    const float* __restrict__ node_mask,
    const float* __restrict__ W_xh,
    const float* __restrict__ b_xh,
    const float* __restrict__ W_pos,
    const float* __restrict__ b_pos,
    float* __restrict__ out)
{
    extern __shared__ float dyn[];
    // phase-1 views
    float2* SjP  = (float2*)dyn;                 // [8][16][32] float2 (32KB)
    float*  a_sm = dyn + 8192;                   // [1024]
    // phase-2 views (reuse)
    float*  sWp  = dyn;                          // [128*96] (48KB)
    float4* S4   = (float4*)(dyn + 12288);       // [128][5] padded quads (flat)

    __shared__ float xi[3][32], xj[3][32];
    __shared__ float mi_sm[32], mj_sm[32];
    __shared__ float wred[8][4];
    __shared__ float sW[XHIN * XHHID];
    __shared__ float sB[XHHID];
    __shared__ float hs[32][6];

    int t = threadIdx.x;
    int w = t >> 5, l = t & 31;

    // ======================= PHASE 1: pair tiles ===========================
    {
        int b = blockIdx.x / NPAIR;
        int p = blockIdx.x % NPAIR;
        int ti = 0, rem = p;
        while (rem >= NTILE - ti) { rem -= NTILE - ti; ti++; }
        int tj = ti + rem;
        bool offdiag = (ti != tj);

        int r = w & 3;
        int g = w >> 2;

        if (t < 32) {
            int rowg = b * NNODE + ti * 32 + t;
            xi[0][t] = xh[rowg * XHIN + 0];
            xi[1][t] = xh[rowg * XHIN + 1];
            xi[2][t] = xh[rowg * XHIN + 2];
            mi_sm[t] = node_mask[rowg];
        } else if (t < 64) {
            int tt = t - 32;
            int rowg = b * NNODE + tj * 32 + tt;
            xj[0][tt] = xh[rowg * XHIN + 0];
            xj[1][tt] = xh[rowg * XHIN + 1];
            xj[2][tt] = xh[rowg * XHIN + 2];
            mj_sm[tt] = node_mask[rowg];
        }

        if (!offdiag) {
            // full-batch masked reduction for mean/N (butterfly)
            int rowg = b * NNODE + t;
            float m  = node_mask[rowg];
            float y0 = xh[rowg * XHIN + 0] * m;
            float y1 = xh[rowg * XHIN + 1] * m;
            float y2 = xh[rowg * XHIN + 2] * m;
            float y3 = m;
            #pragma unroll
            for (int off = 16; off > 0; off >>= 1) {
                y0 += __shfl_xor_sync(0xffffffffu, y0, off);
                y1 += __shfl_xor_sync(0xffffffffu, y1, off);
                y2 += __shfl_xor_sync(0xffffffffu, y2, off);
                y3 += __shfl_xor_sync(0xffffffffu, y3, off);
            }
            if (l == 0) { wred[w][0] = y0; wred[w][1] = y1; wred[w][2] = y2; wred[w][3] = y3; }

            for (int i = t; i < XHIN * XHHID; i += 256) sW[i] = W_xh[i];
            if (t < XHHID) sB[t] = b_xh[t];
            if (t < 192) {
                int rr = t / 6, cc = t % 6;
                hs[rr][cc] = xh[(size_t)(b * NNODE + ti * 32 + rr) * XHIN + 3 + cc];
            }
        }
        __syncthreads();

        if (!offdiag) {
            float sx = 0.f, sy = 0.f, sz = 0.f, sn = 0.f;
            #pragma unroll
            for (int ww = 0; ww < 8; ww++) {
                sx += wred[ww][0]; sy += wred[ww][1];
                sz += wred[ww][2]; sn += wred[ww][3];
            }
            float mean0 = sx / sn, mean1 = sy / sn, mean2 = sz / sn;

            // xh embedding: 2048 outputs, 8 per thread, coalesced over o
            #pragma unroll
            for (int e = 0; e < 8; e++) {
                int v = e * 256 + t;
                int rr = v >> 6, o = v & 63;
                float mr  = mi_sm[rr];
                float xc0 = (xi[0][rr] - mean0) * mr;
                float xc1 = (xi[1][rr] - mean1) * mr;
                float xc2 = (xi[2][rr] - mean2) * mr;
                float acc = sB[o];
                acc = fmaf(xc0,       sW[0 * XHHID + o], acc);
                acc = fmaf(xc1,       sW[1 * XHHID + o], acc);
                acc = fmaf(xc2,       sW[2 * XHHID + o], acc);
                acc = fmaf(hs[rr][0], sW[3 * XHHID + o], acc);
                acc = fmaf(hs[rr][1], sW[4 * XHHID + o], acc);
                acc = fmaf(hs[rr][2], sW[5 * XHHID + o], acc);
                acc = fmaf(hs[rr][3], sW[6 * XHHID + o], acc);
                acc = fmaf(hs[rr][4], sW[7 * XHHID + o], acc);
                acc = fmaf(hs[rr][5], sW[8 * XHHID + o], acc);
                out[(size_t)(b * NNODE + ti * 32 + rr) * 256 + o] = acc * mr;
            }
        }

        // angles for the 32x32 tile (mean cancels in differences)
        #pragma unroll
        for (int k = 0; k < 4; k++) {
            int q = t + k * 256;
            int i = q & 31, j = q >> 5;
            float dx = xi[0][i] - xj[0][j];
            float dy = xi[1][i] - xj[1][j];
            float dz = xi[2][i] - xj[2][j];
            float sq = fmaxf(fmaf(dx, dx, fmaf(dy, dy, dz * dz)), 0.0f);
            a_sm[j * 32 + i] = TWO_PI_F * sqrtf(sq + 1e-12f);
        }
        __syncthreads();

        const float c1 = 0.10381025296522944f;       // log2(100)/64
        float f = exp2f((float)(g * 32 + l) * c1);

        float mi[8];
        #pragma unroll
        for (int k = 0; k < 8; k++) mi[k] = mi_sm[r * 8 + k];

        float ssA[8], ccA[8];
        #pragma unroll
        for (int k = 0; k < 8; k++) { ssA[k] = 0.f; ccA[k] = 0.f; }

        for (int h = 0; h < 2; h++) {
            #pragma unroll 4
            for (int j2 = 0; j2 < 16; j2++) {
                int j = h * 16 + j2;
                float mj = mj_sm[j];
                const float4* ap = (const float4*)&a_sm[j * 32 + r * 8];
                float4 a0 = ap[0];
                float4 a1 = ap[1];
                float av[8] = {a0.x, a0.y, a0.z, a0.w, a1.x, a1.y, a1.z, a1.w};
                float sjs = 0.f, sjc = 0.f;
                #pragma unroll
                for (int k = 0; k < 8; k++) {
                    float ang = av[k] * f;
                    float s = __sinf(ang);
                    float c = __cosf(ang);
                    ssA[k] = fmaf(mj, s, ssA[k]);
                    ccA[k] = fmaf(mj, c, ccA[k]);
                    sjs    = fmaf(mi[k], s, sjs);
                    sjc    = fmaf(mi[k], c, sjc);
                }
                if (offdiag) SjP[(w * 16 + j2) * 32 + l] = make_float2(sjs, sjc);
            }

            if (offdiag) {
                __syncthreads();
                #pragma unroll
                for (int k = 0; k < 4; k++) {
                    int idx = t + k * 256;
                    int gg  = idx >> 9;
                    int jj  = (idx >> 5) & 15;
                    int ll  = idx & 31;
                    float2 v0 = SjP[((gg * 4 + 0) * 16 + jj) * 32 + ll];
                    float2 v1 = SjP[((gg * 4 + 1) * 16 + jj) * 32 + ll];
                    float2 v2 = SjP[((gg * 4 + 2) * 16 + jj) * 32 + ll];
                    float2 v3 = SjP[((gg * 4 + 3) * 16 + jj) * 32 + ll];
                    float ss = (v0.x + v1.x) + (v2.x + v3.x);
                    float cc = (v0.y + v1.y) + (v2.y + v3.y);
                    float* rp = &g_Spart[b][ti][tj * 32 + h * 16 + jj][0];
                    rp[gg * 32 + ll]      = ss;
                    rp[64 + gg * 32 + ll] = cc;
                }
                __syncthreads();
            }
        }

        float* basei = &g_Spart[b][tj][ti * 32][0];
        #pragma unroll
        for (int k = 0; k < 8; k++) {
            float* rp = basei + (r * 8 + k) * 128;
            rp[g * 32 + l]      = ssA[k];
            rp[64 + g * 32 + l] = ccA[k];
        }
    }

    // ======================= GRID BARRIER ==================================
    __syncthreads();
    if (t == 0) {
        __threadfence();
        unsigned old = atomicAdd(&g_ctr, 1u);
        unsigned target = (old / GRIDSZ + 1u) * GRIDSZ;
        volatile unsigned* vc = &g_ctr;
        while (*vc < target) { __nanosleep(64); }
        __threadfence();
    }
    __syncthreads();

    // ======================= PHASE 2: projection GEMM ======================
    if (blockIdx.x < 256) {
        int cb = blockIdx.x & 1;              // col half: cols cb*96 ..
        int rg = blockIdx.x >> 1;             // 0..127
        int b2 = rg >> 4;
        int i0 = (rg & 15) << 4;              // 16 rows

        // stage W_pos half: 128 rows x 24 float4 (48KB)
        {
            const float4* src = (const float4*)W_pos;   // 48 float4 per k-row
            float4*       dst = (float4*)sWp;           // 24 float4 per k-row
            #pragma unroll
            for (int ii = 0; ii < 12; ii++) {
                int idx = t + (ii << 8);                // 0..3071
                int kk = idx / 24, c4 = idx % 24;
                dst[kk * 24 + c4] = src[kk * 48 + cb * 24 + c4];
            }
        }

        // slot sums -> raw S [k][20] padded (L2-hot reads)
        {
            float* Ssc = (float*)S4;
            #pragma unroll
            for (int ii = 0; ii < 8; ii++) {
                int v = t + (ii << 8);                  // 0..2047
                int rv = v >> 7, fv = v & 127;
                float s = 0.f;
                #pragma unroll
                for (int slot = 0; slot < NTILE; slot++)
                    s += g_Spart[b2][slot][i0 + rv][fv];
                Ssc[fv * 20 + rv] = s;
            }
        }

        // N reduction (butterfly; one barrier total in phase 2)
        {
            float m = node_mask[b2 * NNODE + t];
            #pragma unroll
            for (int off = 16; off > 0; off >>= 1)
                m += __shfl_xor_sync(0xffffffffu, m, off);
            if (l == 0) wred[w][0] = m;
        }
        __syncthreads();

        float Ns = 0.f;
        #pragma unroll
        for (int ww = 0; ww < 8; ww++) Ns += wred[ww][0];
        float sc0 = 1.0f / Ns;
        float sc1 = 256.0f / Ns;

        // matvec: thread = (col c of 96, row-octet rh)
        if (t < 192) {
            int rh = t / 96;
            int c  = t - rh * 96;
            float acc[8];
            #pragma unroll
            for (int e = 0; e < 8; e++) acc[e] = 0.f;
            #pragma unroll 4
            for (int k = 0; k < 128; k++) {
                float4 s0 = S4[k * 5 + rh * 2];         // broadcast LDS.128
                float4 s1 = S4[k * 5 + rh * 2 + 1];
                float  wv = sWp[k * 96 + c];            // conflict-free LDS.32
                acc[0] = fmaf(s0.x, wv, acc[0]);
                acc[1] = fmaf(s0.y, wv, acc[1]);
                acc[2] = fmaf(s0.z, wv, acc[2]);
                acc[3] = fmaf(s0.w, wv, acc[3]);
                acc[4] = fmaf(s1.x, wv, acc[4]);
                acc[5] = fmaf(s1.y, wv, acc[5]);
                acc[6] = fmaf(s1.z, wv, acc[6]);
                acc[7] = fmaf(s1.w, wv, acc[7]);
            }
            int col = cb * 96 + c;
            float bp = b_pos[col] * sc1;
            int rbase = b2 * NNODE + i0 + rh * 8;
            #pragma unroll
            for (int e = 0; e < 8; e++) {
                float mke = node_mask[rbase + e];
                out[(size_t)(rbase + e) * 256 + 64 + col]
                    = (acc[e] * sc0 * mke + bp) * mke;
            }
        }
    }
}

extern "C" void kernel_launch(void* const* d_in, const int* in_sizes, int n_in,
                              void* d_out, int out_size)
{
    // inputs (metadata order): t, xh, node_mask, edge_mask, W_xh, b_xh, W_pos, b_pos
    const float* xh        = (const float*)d_in[1];
    const float* node_mask = (const float*)d_in[2];
    const float* W_xh      = (const float*)d_in[4];
    const float* b_xh      = (const float*)d_in[5];
    const float* W_pos     = (const float*)d_in[6];
    const float* b_pos     = (const float*)d_in[7];
    float* out = (float*)d_out;

    cudaFuncSetAttribute(fused_ditemb,
                         cudaFuncAttributeMaxDynamicSharedMemorySize,
                         DYN_BYTES);

    fused_ditemb<<<GRIDSZ, 256, DYN_BYTES>>>(xh, node_mask, W_xh, b_xh,
                                             W_pos, b_pos, out);
}